// round 15
// baseline (speedup 1.0000x reference)
#include <cuda_runtime.h>
#include <cuda_fp16.h>
#include <cstdint>

// sigma = rsqrt( exp(-||z-c_k||^2 * lam_k) @ (W*W) + eps )
// B=262144, K=64, DZ=128, OUT=16.
// f16-split mma.sync + ldmatrix; two-pass K staging (3 CTAs/SM);
// 32x32 warp tiles (halved B-fragment traffic); GEMM2 from V registers
// with partial-beta exchange between col-group warp pairs.

constexpr int K    = 64;
constexpr int DZ   = 128;
constexpr int OUTD = 16;
constexpr int MT   = 128;
constexpr int NTHR = 256;
constexpr float EPS = 1e-6f;

constexpr int SA = 72;   // f16 stride per 64-col pass (36 words = 4 mod 8)
constexpr int SB = 72;
constexpr int SW = 72;

constexpr int OFF_AH  = 0;                        // [128][72] f16
constexpr int OFF_AL  = OFF_AH + MT * SA * 2;     // 18432
constexpr int OFF_BH  = OFF_AL + MT * SA * 2;     // 36864 [64][72]
constexpr int OFF_BL  = OFF_BH + K * SB * 2;      // 46080
constexpr int OFF_WH  = OFF_BL + K * SB * 2;      // 55296 [16][72]
constexpr int OFF_WL  = OFF_WH + OUTD * SW * 2;   // 57600
constexpr int OFF_LAM = OFF_WL + OUTD * SW * 2;   // 59904
constexpr int OFF_C2  = OFF_LAM + 256;
constexpr int OFF_Z2  = OFF_C2 + 256;
constexpr int OFF_EX  = 61440;                    // partial-beta exchange, 8KB
constexpr int SMEM_BYTES = OFF_EX + 8192;         // 69632 (3 CTAs/SM fits)

__device__ __forceinline__ uint32_t smem_u32(const void* p) {
    uint32_t a;
    asm("{ .reg .u64 t; cvta.to.shared.u64 t, %1; cvt.u32.u64 %0, t; }" : "=r"(a) : "l"(p));
    return a;
}
__device__ __forceinline__ void ldsm4(uint32_t* r, uint32_t a) {
    asm volatile("ldmatrix.sync.aligned.m8n8.x4.shared.b16 {%0,%1,%2,%3}, [%4];"
                 : "=r"(r[0]), "=r"(r[1]), "=r"(r[2]), "=r"(r[3]) : "r"(a));
}
__device__ __forceinline__ void mma16816(float* c, const uint32_t* a,
                                         uint32_t b0, uint32_t b1) {
    asm volatile(
        "mma.sync.aligned.m16n8k16.row.col.f32.f16.f16.f32 "
        "{%0,%1,%2,%3}, {%4,%5,%6,%7}, {%8,%9}, {%0,%1,%2,%3};"
        : "+f"(c[0]), "+f"(c[1]), "+f"(c[2]), "+f"(c[3])
        : "r"(a[0]), "r"(a[1]), "r"(a[2]), "r"(a[3]), "r"(b0), "r"(b1));
}
__device__ __forceinline__ uint32_t split_pack2(float f0, float f1, uint32_t& lo_pack) {
    __half h0 = __float2half_rn(f0);
    __half h1 = __float2half_rn(f1);
    __half l0 = __float2half_rn(f0 - __half2float(h0));
    __half l1 = __float2half_rn(f1 - __half2float(h1));
    lo_pack = (uint32_t)__half_as_ushort(l0) | ((uint32_t)__half_as_ushort(l1) << 16);
    return (uint32_t)__half_as_ushort(h0) | ((uint32_t)__half_as_ushort(h1) << 16);
}

__global__ __launch_bounds__(NTHR, 3)
void varnet_hmma(const float* __restrict__ z,
                 const float* __restrict__ cnts,
                 const float* __restrict__ lams,
                 const float* __restrict__ W,
                 float* __restrict__ out,
                 int B)
{
    extern __shared__ __align__(16) char smem[];
    const uint32_t sb = smem_u32(smem);
    float* s_lam = reinterpret_cast<float*>(smem + OFF_LAM);
    float* s_c2  = reinterpret_cast<float*>(smem + OFF_C2);
    float* s_z2  = reinterpret_cast<float*>(smem + OFF_Z2);

    const int t    = threadIdx.x;
    const int wid  = t >> 5;
    const int lane = t & 31;
    const int gid  = lane >> 2;
    const int tig  = lane & 3;
    const int row0 = blockIdx.x * MT;
    const int rg   = wid & 3;     // row group: rows 32*rg .. +31
    const int cg   = wid >> 2;    // col group: centers 32*cg .. +31

    // staging roles
    const int zr_  = t >> 1;          // z row 0..127
    const int zh_  = t & 1;           // 32-col half within the pass
    const int cr_  = t >> 2;          // cnts row 0..63
    const int cq_  = t & 3;           // 16-col quarter within the pass

    const long long zrow = (long long)row0 + zr_;
    const float* zptr = z + zrow * DZ;
    const float* cptr = cnts + cr_ * DZ;

    float z2acc = 0.f, c2acc = 0.f;

    // GEMM1 accumulators: [m-tile][n-tile][quad]
    float acc[2][4][4];
    #pragma unroll
    for (int m = 0; m < 2; m++)
        #pragma unroll
        for (int nt = 0; nt < 4; nt++)
            #pragma unroll
            for (int q = 0; q < 4; q++) acc[m][nt][q] = 0.f;

    const uint32_t aA = sb + OFF_AH +
        (uint32_t)(((32 * rg + (lane & 15)) * SA + 8 * ((lane >> 4) & 1)) * 2);
    const uint32_t aAl = aA + (OFF_AL - OFF_AH);
    constexpr uint32_t M2 = (uint32_t)(16 * SA * 2);   // second m-tile offset
    const uint32_t laneB =
        (uint32_t)(((32 * cg + (lane & 7) + 8 * ((lane >> 4) & 1)) * SB
                    + 8 * ((lane >> 3) & 1)) * 2);
    const uint32_t aB  = sb + OFF_BH + laneB;
    const uint32_t aBl = sb + OFF_BL + laneB;
    constexpr uint32_t BP = (uint32_t)(16 * SB * 2);   // n-tile-pair stride

    #pragma unroll
    for (int pass = 0; pass < 2; pass++) {
        const int kb = 64 * pass;

        if (pass == 1) __syncthreads();   // GEMM pass-0 reads done before restage

        // ---- stage z: 8 f4 per thread, 2 batches of 4 (MLP=4) ----
        #pragma unroll
        for (int b = 0; b < 2; b++) {
            float4 v[4];
            #pragma unroll
            for (int i = 0; i < 4; i++) {
                const int j = (b * 4 + i + zr_) & 7;
                const int d = kb + 32 * zh_ + 4 * j;
                v[i] = (zrow < B)
                    ? *reinterpret_cast<const float4*>(zptr + d)
                    : make_float4(0.f, 0.f, 0.f, 0.f);
            }
            #pragma unroll
            for (int i = 0; i < 4; i++) {
                const int j = (b * 4 + i + zr_) & 7;
                const float4 vv = v[i];
                z2acc = fmaf(vv.x, vv.x, fmaf(vv.y, vv.y,
                        fmaf(vv.z, vv.z, fmaf(vv.w, vv.w, z2acc))));
                uint32_t l0, l1;
                uint32_t h0 = split_pack2(vv.x, vv.y, l0);
                uint32_t h1 = split_pack2(vv.z, vv.w, l1);
                const int byo = (zr_ * SA + 32 * zh_ + 4 * j) * 2;
                *reinterpret_cast<uint64_t*>(smem + OFF_AH + byo) =
                    (uint64_t)h0 | ((uint64_t)h1 << 32);
                *reinterpret_cast<uint64_t*>(smem + OFF_AL + byo) =
                    (uint64_t)l0 | ((uint64_t)l1 << 32);
            }
        }

        // ---- stage 2*cnts: 4 f4 per thread, one batch (MLP=4) ----
        {
            float4 v[4];
            #pragma unroll
            for (int i = 0; i < 4; i++) {
                const int j = (i + cr_) & 3;
                v[i] = *reinterpret_cast<const float4*>(cptr + kb + 16 * cq_ + 4 * j);
            }
            #pragma unroll
            for (int i = 0; i < 4; i++) {
                const int j = (i + cr_) & 3;
                const float4 vv = v[i];
                c2acc = fmaf(vv.x, vv.x, fmaf(vv.y, vv.y,
                        fmaf(vv.z, vv.z, fmaf(vv.w, vv.w, c2acc))));
                uint32_t l0, l1;
                uint32_t h0 = split_pack2(2.f * vv.x, 2.f * vv.y, l0);
                uint32_t h1 = split_pack2(2.f * vv.z, 2.f * vv.w, l1);
                const int byo = (cr_ * SB + 16 * cq_ + 4 * j) * 2;
                *reinterpret_cast<uint64_t*>(smem + OFF_BH + byo) =
                    (uint64_t)h0 | ((uint64_t)h1 << 32);
                *reinterpret_cast<uint64_t*>(smem + OFF_BL + byo) =
                    (uint64_t)l0 | ((uint64_t)l1 << 32);
            }
        }

        // ---- pass-0 only: W^2 + lam; pass-1: finalize z2/c2 ----
        if (pass == 0) {
            #pragma unroll
            for (int i = 0; i < 4; i++) {
                const int idx = t * 4 + i;     // W [64][16] row-major
                const int kc = idx >> 4, j = idx & 15;
                float w = W[idx];
                float w2 = w * w;
                __half hh = __float2half_rn(w2);
                __half hl = __float2half_rn(w2 - __half2float(hh));
                const int byo = (j * SW + kc) * 2;
                *reinterpret_cast<uint16_t*>(smem + OFF_WH + byo) = __half_as_ushort(hh);
                *reinterpret_cast<uint16_t*>(smem + OFF_WL + byo) = __half_as_ushort(hl);
            }
            if (t < K) s_lam[t] = lams[t];
        } else {
            float zs = z2acc + __shfl_xor_sync(0xFFFFFFFFu, z2acc, 1);
            if (zh_ == 0) s_z2[zr_] = zs;
            float cs = c2acc;
            cs += __shfl_xor_sync(0xFFFFFFFFu, cs, 1);
            cs += __shfl_xor_sync(0xFFFFFFFFu, cs, 2);
            if (cq_ == 0) s_c2[cr_] = cs;
        }
        __syncthreads();

        // ---- GEMM pass: 4 k-steps over this 64-col chunk, 32x32 warp tile ----
        #pragma unroll
        for (int s = 0; s < 4; s++) {
            const uint32_t ks = (uint32_t)(32 * s);
            uint32_t ah[2][4], al[2][4];
            ldsm4(ah[0], aA  + ks);
            ldsm4(ah[1], aA  + M2 + ks);
            ldsm4(al[0], aAl + ks);
            ldsm4(al[1], aAl + M2 + ks);
            #pragma unroll
            for (int p = 0; p < 2; p++) {
                uint32_t bh[4], bl[4];
                ldsm4(bh, aB  + (uint32_t)p * BP + ks);
                ldsm4(bl, aBl + (uint32_t)p * BP + ks);
                #pragma unroll
                for (int m = 0; m < 2; m++) {
                    float* c0 = acc[m][2 * p];
                    float* c1 = acc[m][2 * p + 1];
                    mma16816(c0, ah[m], bh[0], bh[1]);
                    mma16816(c0, ah[m], bl[0], bl[1]);
                    mma16816(c0, al[m], bh[0], bh[1]);
                    mma16816(c1, ah[m], bh[2], bh[3]);
                    mma16816(c1, ah[m], bl[2], bl[3]);
                    mma16816(c1, al[m], bh[2], bh[3]);
                }
            }
        }
    }

    // ===== epilogue 1: V = exp(-lam*(z2+c2-dot)), pack to f16x2 registers =====
    uint32_t vpack[2][4][2];
    #pragma unroll
    for (int m = 0; m < 2; m++) {
        const int rA0 = 32 * rg + 16 * m + gid;
        const float z20 = s_z2[rA0];
        const float z21 = s_z2[rA0 + 8];
        #pragma unroll
        for (int nt = 0; nt < 4; nt++) {
            const int n0 = 32 * cg + 8 * nt + 2 * tig;
            const float c20 = s_c2[n0], c21 = s_c2[n0 + 1];
            const float lm0 = s_lam[n0], lm1 = s_lam[n0 + 1];
            float v00 = __expf(-lm0 * (z20 + c20 - acc[m][nt][0]));
            float v01 = __expf(-lm1 * (z20 + c21 - acc[m][nt][1]));
            float v10 = __expf(-lm0 * (z21 + c20 - acc[m][nt][2]));
            float v11 = __expf(-lm1 * (z21 + c21 - acc[m][nt][3]));
            __half a0 = __float2half_rn(v00), a1 = __float2half_rn(v01);
            __half b0 = __float2half_rn(v10), b1 = __float2half_rn(v11);
            vpack[m][nt][0] = (uint32_t)__half_as_ushort(a0) |
                              ((uint32_t)__half_as_ushort(a1) << 16);
            vpack[m][nt][1] = (uint32_t)__half_as_ushort(b0) |
                              ((uint32_t)__half_as_ushort(b1) << 16);
        }
    }

    // ===== GEMM2 partial: beta contribution from this warp's 32 centers =====
    float acc2[2][2][4];
    #pragma unroll
    for (int m = 0; m < 2; m++)
        #pragma unroll
        for (int n = 0; n < 2; n++)
            #pragma unroll
            for (int q = 0; q < 4; q++) acc2[m][n][q] = 0.f;
    {
        const uint32_t laneW =
            (uint32_t)((((lane & 7) + 8 * ((lane >> 4) & 1)) * SW + 8 * ((lane >> 3) & 1)) * 2);
        const uint32_t aW  = sb + OFF_WH + laneW;
        const uint32_t aWl = sb + OFF_WL + laneW;

        #pragma unroll
        for (int q = 0; q < 2; q++) {
            const int s = 2 * cg + q;                 // global k-step (16 centers)
            const uint32_t ks = (uint32_t)(32 * s);
            uint32_t wh[4], wl[4];
            ldsm4(wh, aW  + ks);
            ldsm4(wl, aWl + ks);
            #pragma unroll
            for (int m = 0; m < 2; m++) {
                uint32_t av[4] = { vpack[m][2 * q][0],     vpack[m][2 * q][1],
                                   vpack[m][2 * q + 1][0], vpack[m][2 * q + 1][1] };
                mma16816(acc2[m][0], av, wh[0], wh[1]);
                mma16816(acc2[m][0], av, wl[0], wl[1]);
                mma16816(acc2[m][1], av, wh[2], wh[3]);
                mma16816(acc2[m][1], av, wl[2], wl[3]);
            }
        }
    }

    // ===== partial-beta exchange: warp pair (rg, cg) <-> (rg, 1-cg) =====
    // Each warp finalizes m-tile == cg; hands off m-tile (1-cg) to partner.
    {
        const int mo = 1 - cg;
        float4* ex = reinterpret_cast<float4*>(smem + OFF_EX + wid * 1024 + lane * 32);
        ex[0] = make_float4(acc2[mo][0][0], acc2[mo][0][1], acc2[mo][0][2], acc2[mo][0][3]);
        ex[1] = make_float4(acc2[mo][1][0], acc2[mo][1][1], acc2[mo][1][2], acc2[mo][1][3]);
    }
    __syncthreads();
    {
        const float4* pex = reinterpret_cast<const float4*>(
            smem + OFF_EX + (wid ^ 4) * 1024 + lane * 32);
        float4 p0 = pex[0], p1 = pex[1];
        acc2[cg][0][0] += p0.x; acc2[cg][0][1] += p0.y;
        acc2[cg][0][2] += p0.z; acc2[cg][0][3] += p0.w;
        acc2[cg][1][0] += p1.x; acc2[cg][1][1] += p1.y;
        acc2[cg][1][2] += p1.z; acc2[cg][1][3] += p1.w;
    }

    // ===== epilogue 2: sigma = rsqrt(beta+eps), store 16 rows per warp =====
    {
        const int r0 = 32 * rg + 16 * cg;
        const long long g0 = (long long)row0 + r0 + gid;
        const long long g1 = g0 + 8;
        #pragma unroll
        for (int n = 0; n < 2; n++) {
            const int j0 = n * 8 + tig * 2;
            if (g0 < B) {
                float2 o = make_float2(rsqrtf(acc2[cg][n][0] + EPS),
                                       rsqrtf(acc2[cg][n][1] + EPS));
                *reinterpret_cast<float2*>(out + g0 * OUTD + j0) = o;
            }
            if (g1 < B) {
                float2 o = make_float2(rsqrtf(acc2[cg][n][2] + EPS),
                                       rsqrtf(acc2[cg][n][3] + EPS));
                *reinterpret_cast<float2*>(out + g1 * OUTD + j0) = o;
            }
        }
    }
}

extern "C" void kernel_launch(void* const* d_in, const int* in_sizes, int n_in,
                              void* d_out, int out_size)
{
    const float* z    = (const float*)d_in[0];
    const float* cnts = (const float*)d_in[1];
    const float* lams = (const float*)d_in[2];
    const float* W    = (const float*)d_in[3];
    float* out = (float*)d_out;

    const int B = in_sizes[0] / DZ;
    cudaFuncSetAttribute(varnet_hmma,
                         cudaFuncAttributeMaxDynamicSharedMemorySize, SMEM_BYTES);
    const int grid = (B + MT - 1) / MT;
    varnet_hmma<<<grid, NTHR, SMEM_BYTES>>>(z, cnts, lams, W, out, B);
}

// round 16
// speedup vs baseline: 1.0010x; 1.0010x over previous
#include <cuda_runtime.h>
#include <cuda_fp16.h>
#include <cstdint>

// sigma = rsqrt( exp(-||z-c_k||^2 * lam_k) @ (W*W) + eps )
// B=262144, K=64, DZ=128, OUT=16.
// f16-split mma.sync + ldmatrix; two-pass K staging (3 CTAs/SM);
// 32x32 warp tiles; register-lean sequential-m epilogue (anti-spill);
// GEMM2 from V registers + partial-beta exchange between warp pairs.

constexpr int K    = 64;
constexpr int DZ   = 128;
constexpr int OUTD = 16;
constexpr int MT   = 128;
constexpr int NTHR = 256;
constexpr float EPS = 1e-6f;

constexpr int SA = 72;   // f16 stride per 64-col pass (36 words = 4 mod 8)
constexpr int SB = 72;
constexpr int SW = 72;

constexpr int OFF_AH  = 0;                        // [128][72] f16
constexpr int OFF_AL  = OFF_AH + MT * SA * 2;     // 18432
constexpr int OFF_BH  = OFF_AL + MT * SA * 2;     // 36864 [64][72]
constexpr int OFF_BL  = OFF_BH + K * SB * 2;      // 46080
constexpr int OFF_WH  = OFF_BL + K * SB * 2;      // 55296 [16][72]
constexpr int OFF_WL  = OFF_WH + OUTD * SW * 2;   // 57600
constexpr int OFF_LAM = OFF_WL + OUTD * SW * 2;   // 59904
constexpr int OFF_C2  = OFF_LAM + 256;
constexpr int OFF_Z2  = OFF_C2 + 256;
constexpr int OFF_EX  = 61440;                    // partial-beta exchange, 8KB
constexpr int SMEM_BYTES = OFF_EX + 8192;         // 69632 (3 CTAs/SM fits)

__device__ __forceinline__ uint32_t smem_u32(const void* p) {
    uint32_t a;
    asm("{ .reg .u64 t; cvta.to.shared.u64 t, %1; cvt.u32.u64 %0, t; }" : "=r"(a) : "l"(p));
    return a;
}
__device__ __forceinline__ void ldsm4(uint32_t* r, uint32_t a) {
    asm volatile("ldmatrix.sync.aligned.m8n8.x4.shared.b16 {%0,%1,%2,%3}, [%4];"
                 : "=r"(r[0]), "=r"(r[1]), "=r"(r[2]), "=r"(r[3]) : "r"(a));
}
__device__ __forceinline__ void mma16816(float* c, const uint32_t* a,
                                         uint32_t b0, uint32_t b1) {
    asm volatile(
        "mma.sync.aligned.m16n8k16.row.col.f32.f16.f16.f32 "
        "{%0,%1,%2,%3}, {%4,%5,%6,%7}, {%8,%9}, {%0,%1,%2,%3};"
        : "+f"(c[0]), "+f"(c[1]), "+f"(c[2]), "+f"(c[3])
        : "r"(a[0]), "r"(a[1]), "r"(a[2]), "r"(a[3]), "r"(b0), "r"(b1));
}
__device__ __forceinline__ uint32_t split_pack2(float f0, float f1, uint32_t& lo_pack) {
    __half h0 = __float2half_rn(f0);
    __half h1 = __float2half_rn(f1);
    __half l0 = __float2half_rn(f0 - __half2float(h0));
    __half l1 = __float2half_rn(f1 - __half2float(h1));
    lo_pack = (uint32_t)__half_as_ushort(l0) | ((uint32_t)__half_as_ushort(l1) << 16);
    return (uint32_t)__half_as_ushort(h0) | ((uint32_t)__half_as_ushort(h1) << 16);
}

__global__ __launch_bounds__(NTHR, 3)
void varnet_hmma(const float* __restrict__ z,
                 const float* __restrict__ cnts,
                 const float* __restrict__ lams,
                 const float* __restrict__ W,
                 float* __restrict__ out,
                 int B)
{
    extern __shared__ __align__(16) char smem[];
    const uint32_t sb = smem_u32(smem);
    float* s_lam = reinterpret_cast<float*>(smem + OFF_LAM);
    float* s_c2  = reinterpret_cast<float*>(smem + OFF_C2);
    float* s_z2  = reinterpret_cast<float*>(smem + OFF_Z2);

    const int t    = threadIdx.x;
    const int wid  = t >> 5;
    const int lane = t & 31;
    const int gid  = lane >> 2;
    const int tig  = lane & 3;
    const int row0 = blockIdx.x * MT;
    const int rg   = wid & 3;     // row group: rows 32*rg .. +31
    const int cg   = wid >> 2;    // col group: centers 32*cg .. +31

    // staging roles
    const int zr_  = t >> 1;          // z row 0..127
    const int zh_  = t & 1;           // 32-col half within the pass
    const int cr_  = t >> 2;          // cnts row 0..63
    const int cq_  = t & 3;           // 16-col quarter within the pass

    const long long zrow = (long long)row0 + zr_;
    const float* zptr = z + zrow * DZ;
    const float* cptr = cnts + cr_ * DZ;

    float z2acc = 0.f, c2acc = 0.f;

    // GEMM1 accumulators: [m-tile][n-tile][quad]
    float acc[2][4][4];
    #pragma unroll
    for (int m = 0; m < 2; m++)
        #pragma unroll
        for (int nt = 0; nt < 4; nt++)
            #pragma unroll
            for (int q = 0; q < 4; q++) acc[m][nt][q] = 0.f;

    const uint32_t aA = sb + OFF_AH +
        (uint32_t)(((32 * rg + (lane & 15)) * SA + 8 * ((lane >> 4) & 1)) * 2);
    const uint32_t aAl = aA + (OFF_AL - OFF_AH);
    constexpr uint32_t M2 = (uint32_t)(16 * SA * 2);   // second m-tile offset
    const uint32_t laneB =
        (uint32_t)(((32 * cg + (lane & 7) + 8 * ((lane >> 4) & 1)) * SB
                    + 8 * ((lane >> 3) & 1)) * 2);
    const uint32_t aB  = sb + OFF_BH + laneB;
    const uint32_t aBl = sb + OFF_BL + laneB;
    constexpr uint32_t BP = (uint32_t)(16 * SB * 2);   // n-tile-pair stride

    #pragma unroll
    for (int pass = 0; pass < 2; pass++) {
        const int kb = 64 * pass;

        if (pass == 1) __syncthreads();   // GEMM pass-0 reads done before restage

        // ---- stage z: 8 f4 per thread, 2 batches of 4 (MLP=4) ----
        #pragma unroll
        for (int b = 0; b < 2; b++) {
            float4 v[4];
            #pragma unroll
            for (int i = 0; i < 4; i++) {
                const int j = (b * 4 + i + zr_) & 7;
                const int d = kb + 32 * zh_ + 4 * j;
                v[i] = (zrow < B)
                    ? *reinterpret_cast<const float4*>(zptr + d)
                    : make_float4(0.f, 0.f, 0.f, 0.f);
            }
            #pragma unroll
            for (int i = 0; i < 4; i++) {
                const int j = (b * 4 + i + zr_) & 7;
                const float4 vv = v[i];
                z2acc = fmaf(vv.x, vv.x, fmaf(vv.y, vv.y,
                        fmaf(vv.z, vv.z, fmaf(vv.w, vv.w, z2acc))));
                uint32_t l0, l1;
                uint32_t h0 = split_pack2(vv.x, vv.y, l0);
                uint32_t h1 = split_pack2(vv.z, vv.w, l1);
                const int byo = (zr_ * SA + 32 * zh_ + 4 * j) * 2;
                *reinterpret_cast<uint64_t*>(smem + OFF_AH + byo) =
                    (uint64_t)h0 | ((uint64_t)h1 << 32);
                *reinterpret_cast<uint64_t*>(smem + OFF_AL + byo) =
                    (uint64_t)l0 | ((uint64_t)l1 << 32);
            }
        }

        // ---- stage 2*cnts: 4 f4 per thread, one batch (MLP=4) ----
        {
            float4 v[4];
            #pragma unroll
            for (int i = 0; i < 4; i++) {
                const int j = (i + cr_) & 3;
                v[i] = *reinterpret_cast<const float4*>(cptr + kb + 16 * cq_ + 4 * j);
            }
            #pragma unroll
            for (int i = 0; i < 4; i++) {
                const int j = (i + cr_) & 3;
                const float4 vv = v[i];
                c2acc = fmaf(vv.x, vv.x, fmaf(vv.y, vv.y,
                        fmaf(vv.z, vv.z, fmaf(vv.w, vv.w, c2acc))));
                uint32_t l0, l1;
                uint32_t h0 = split_pack2(2.f * vv.x, 2.f * vv.y, l0);
                uint32_t h1 = split_pack2(2.f * vv.z, 2.f * vv.w, l1);
                const int byo = (cr_ * SB + 16 * cq_ + 4 * j) * 2;
                *reinterpret_cast<uint64_t*>(smem + OFF_BH + byo) =
                    (uint64_t)h0 | ((uint64_t)h1 << 32);
                *reinterpret_cast<uint64_t*>(smem + OFF_BL + byo) =
                    (uint64_t)l0 | ((uint64_t)l1 << 32);
            }
        }

        // ---- pass-0 only: W^2 + lam; pass-1: finalize z2/c2 ----
        if (pass == 0) {
            #pragma unroll
            for (int i = 0; i < 4; i++) {
                const int idx = t * 4 + i;     // W [64][16] row-major
                const int kc = idx >> 4, j = idx & 15;
                float w = W[idx];
                float w2 = w * w;
                __half hh = __float2half_rn(w2);
                __half hl = __float2half_rn(w2 - __half2float(hh));
                const int byo = (j * SW + kc) * 2;
                *reinterpret_cast<uint16_t*>(smem + OFF_WH + byo) = __half_as_ushort(hh);
                *reinterpret_cast<uint16_t*>(smem + OFF_WL + byo) = __half_as_ushort(hl);
            }
            if (t < K) s_lam[t] = lams[t];
        } else {
            float zs = z2acc + __shfl_xor_sync(0xFFFFFFFFu, z2acc, 1);
            if (zh_ == 0) s_z2[zr_] = zs;
            float cs = c2acc;
            cs += __shfl_xor_sync(0xFFFFFFFFu, cs, 1);
            cs += __shfl_xor_sync(0xFFFFFFFFu, cs, 2);
            if (cq_ == 0) s_c2[cr_] = cs;
        }
        __syncthreads();

        // ---- GEMM pass: 4 k-steps over this 64-col chunk, 32x32 warp tile ----
        #pragma unroll
        for (int s = 0; s < 4; s++) {
            const uint32_t ks = (uint32_t)(32 * s);
            uint32_t ah[2][4], al[2][4];
            ldsm4(ah[0], aA  + ks);
            ldsm4(ah[1], aA  + M2 + ks);
            ldsm4(al[0], aAl + ks);
            ldsm4(al[1], aAl + M2 + ks);
            #pragma unroll
            for (int p = 0; p < 2; p++) {
                uint32_t bh[4], bl[4];
                ldsm4(bh, aB  + (uint32_t)p * BP + ks);
                ldsm4(bl, aBl + (uint32_t)p * BP + ks);
                #pragma unroll
                for (int m = 0; m < 2; m++) {
                    float* c0 = acc[m][2 * p];
                    float* c1 = acc[m][2 * p + 1];
                    mma16816(c0, ah[m], bh[0], bh[1]);
                    mma16816(c0, ah[m], bl[0], bl[1]);
                    mma16816(c0, al[m], bh[0], bh[1]);
                    mma16816(c1, ah[m], bh[2], bh[3]);
                    mma16816(c1, ah[m], bl[2], bl[3]);
                    mma16816(c1, al[m], bh[2], bh[3]);
                }
            }
        }
    }

    // ===== epilogue + GEMM2, m-tiles processed SEQUENTIALLY (register-lean):
    // per m: V from acc[m] -> vpack[4][2] (8 regs), consumed immediately by
    // the GEMM2 partial for this m. W fragments loaded per (m,q) so they
    // live only across 4 MMAs. acc[m] dies as consumed.
    float acc2[2][2][4];   // [m][n][quad] partial betas (this warp's 32 centers)
    {
        const uint32_t laneW =
            (uint32_t)((((lane & 7) + 8 * ((lane >> 4) & 1)) * SW + 8 * ((lane >> 3) & 1)) * 2);
        const uint32_t aW  = sb + OFF_WH + laneW;
        const uint32_t aWl = sb + OFF_WL + laneW;

        #pragma unroll
        for (int m = 0; m < 2; m++) {
            uint32_t vpack[4][2];
            const int rA0 = 32 * rg + 16 * m + gid;
            const float z20 = s_z2[rA0];
            const float z21 = s_z2[rA0 + 8];
            #pragma unroll
            for (int nt = 0; nt < 4; nt++) {
                const int n0 = 32 * cg + 8 * nt + 2 * tig;
                const float c20 = s_c2[n0], c21 = s_c2[n0 + 1];
                const float lm0 = s_lam[n0], lm1 = s_lam[n0 + 1];
                float v00 = __expf(-lm0 * (z20 + c20 - acc[m][nt][0]));
                float v01 = __expf(-lm1 * (z20 + c21 - acc[m][nt][1]));
                float v10 = __expf(-lm0 * (z21 + c20 - acc[m][nt][2]));
                float v11 = __expf(-lm1 * (z21 + c21 - acc[m][nt][3]));
                __half a0 = __float2half_rn(v00), a1 = __float2half_rn(v01);
                __half b0 = __float2half_rn(v10), b1 = __float2half_rn(v11);
                vpack[nt][0] = (uint32_t)__half_as_ushort(a0) |
                               ((uint32_t)__half_as_ushort(a1) << 16);
                vpack[nt][1] = (uint32_t)__half_as_ushort(b0) |
                               ((uint32_t)__half_as_ushort(b1) << 16);
            }
            #pragma unroll
            for (int n = 0; n < 2; n++)
                #pragma unroll
                for (int q = 0; q < 4; q++) acc2[m][n][q] = 0.f;
            #pragma unroll
            for (int q = 0; q < 2; q++) {
                const int s = 2 * cg + q;                 // global k-step
                const uint32_t ks = (uint32_t)(32 * s);
                uint32_t wh[4], wl[4];
                ldsm4(wh, aW  + ks);
                ldsm4(wl, aWl + ks);
                uint32_t av[4] = { vpack[2 * q][0],     vpack[2 * q][1],
                                   vpack[2 * q + 1][0], vpack[2 * q + 1][1] };
                mma16816(acc2[m][0], av, wh[0], wh[1]);
                mma16816(acc2[m][0], av, wl[0], wl[1]);
                mma16816(acc2[m][1], av, wh[2], wh[3]);
                mma16816(acc2[m][1], av, wl[2], wl[3]);
            }
        }
    }

    // ===== partial-beta exchange: warp pair (rg, cg) <-> (rg, 1-cg) =====
    {
        const int mo = 1 - cg;
        float4* ex = reinterpret_cast<float4*>(smem + OFF_EX + wid * 1024 + lane * 32);
        ex[0] = make_float4(acc2[mo][0][0], acc2[mo][0][1], acc2[mo][0][2], acc2[mo][0][3]);
        ex[1] = make_float4(acc2[mo][1][0], acc2[mo][1][1], acc2[mo][1][2], acc2[mo][1][3]);
    }
    __syncthreads();
    {
        const float4* pex = reinterpret_cast<const float4*>(
            smem + OFF_EX + (wid ^ 4) * 1024 + lane * 32);
        float4 p0 = pex[0], p1 = pex[1];
        acc2[cg][0][0] += p0.x; acc2[cg][0][1] += p0.y;
        acc2[cg][0][2] += p0.z; acc2[cg][0][3] += p0.w;
        acc2[cg][1][0] += p1.x; acc2[cg][1][1] += p1.y;
        acc2[cg][1][2] += p1.z; acc2[cg][1][3] += p1.w;
    }

    // ===== epilogue 2: sigma = rsqrt(beta+eps), store 16 rows per warp =====
    {
        const int r0 = 32 * rg + 16 * cg;
        const long long g0 = (long long)row0 + r0 + gid;
        const long long g1 = g0 + 8;
        #pragma unroll
        for (int n = 0; n < 2; n++) {
            const int j0 = n * 8 + tig * 2;
            if (g0 < B) {
                float2 o = make_float2(rsqrtf(acc2[cg][n][0] + EPS),
                                       rsqrtf(acc2[cg][n][1] + EPS));
                *reinterpret_cast<float2*>(out + g0 * OUTD + j0) = o;
            }
            if (g1 < B) {
                float2 o = make_float2(rsqrtf(acc2[cg][n][2] + EPS),
                                       rsqrtf(acc2[cg][n][3] + EPS));
                *reinterpret_cast<float2*>(out + g1 * OUTD + j0) = o;
            }
        }
    }
}

extern "C" void kernel_launch(void* const* d_in, const int* in_sizes, int n_in,
                              void* d_out, int out_size)
{
    const float* z    = (const float*)d_in[0];
    const float* cnts = (const float*)d_in[1];
    const float* lams = (const float*)d_in[2];
    const float* W    = (const float*)d_in[3];
    float* out = (float*)d_out;

    const int B = in_sizes[0] / DZ;
    cudaFuncSetAttribute(varnet_hmma,
                         cudaFuncAttributeMaxDynamicSharedMemorySize, SMEM_BYTES);
    const int grid = (B + MT - 1) / MT;
    varnet_hmma<<<grid, NTHR, SMEM_BYTES>>>(z, cnts, lams, W, out, B);
}